// round 16
// baseline (speedup 1.0000x reference)
#include <cuda_runtime.h>
#include <cuda_fp16.h>
#include <math.h>
#include <stdint.h>

#define TOK    16384
#define DMODEL 1024
#define DFF    2048
#define TSEQ   512
#define TDSZ   (TSEQ*DMODEL)

// ------------------------- scratch (device globals; no allocs) -------------
__device__ __half g_ln  [TOK*DMODEL];
__device__ __half g_wide[TOK*DFF];
__device__ __half g_dy  [TOK*DMODEL];
__device__ __half g_c1  [TOK*DMODEL];
__device__ __half g_qh  [TOK*DMODEL];
__device__ __half g_kh  [TOK*DMODEL];
__device__ __half g_vh  [TOK*DMODEL];
__device__ __half g_vt  [TOK*DMODEL];
__device__ float  g_y   [TOK*DMODEL];
__device__ float  g_y2  [TOK*DMODEL];
__device__ __half g_MT   [DMODEL*DMODEL];
__device__ __half g_MinvA[DMODEL*DMODEL];
__device__ __half g_W1fT [DFF*DMODEL];
__device__ __half g_W2fT [DMODEL*DFF];
__device__ float  g_b2f  [DMODEL];
__device__ __half g_Bc1t [DMODEL*3*DMODEL];
__device__ __half g_Bc2t [DMODEL*3*DMODEL];
__device__ __half g_qwt  [DMODEL*DMODEL];
__device__ __half g_kwt  [DMODEL*DMODEL];
__device__ __half g_vwt  [DMODEL*DMODEL];
__device__ __half g_lin1t[DFF*DMODEL];
__device__ __half g_lin2r[DFF*DMODEL];
__device__ __half g_m11t [DFF*DMODEL];
__device__ __half g_m12t [DMODEL*DFF];
__device__ __half g_m21t [DFF*DMODEL];
__device__ __half g_m22t [DMODEL*DFF];

// ------------------------- helpers ----------------------------------------
__device__ __forceinline__ void mma16(float* d, const uint32_t* a, const uint32_t* b){
  asm volatile(
    "mma.sync.aligned.m16n8k16.row.col.f32.f16.f16.f32 "
    "{%0,%1,%2,%3}, {%4,%5,%6,%7}, {%8,%9}, {%0,%1,%2,%3};"
    : "+f"(d[0]), "+f"(d[1]), "+f"(d[2]), "+f"(d[3])
    : "r"(a[0]), "r"(a[1]), "r"(a[2]), "r"(a[3]), "r"(b[0]), "r"(b[1]));
}
#define LDSM4(r0,r1,r2,r3,addr) \
  asm volatile("ldmatrix.sync.aligned.m8n8.x4.shared.b16 {%0,%1,%2,%3}, [%4];" \
               : "=r"(r0), "=r"(r1), "=r"(r2), "=r"(r3) : "r"(addr))
__device__ __forceinline__ void cp16(void* sdst, const void* gsrc, bool pred){
  uint32_t s = (uint32_t)__cvta_generic_to_shared(sdst);
  int n = pred ? 16 : 0;
  asm volatile("cp.async.cg.shared.global [%0], [%1], 16, %2;" :: "r"(s), "l"(gsrc), "r"(n));
}
__device__ __forceinline__ void cp_commit(){ asm volatile("cp.async.commit_group;"); }
template<int N> __device__ __forceinline__ void cp_wait(){
  asm volatile("cp.async.wait_group %0;" :: "n"(N));
}
__device__ __forceinline__ float gelu_f(float x){
  return 0.5f*x*(1.f + erff(x*0.70710678118654752f));
}
__device__ __forceinline__ float silu_f(float x){ return x/(1.f+expf(-x)); }
__device__ __forceinline__ uint32_t s2u32(const void* p){
  return (uint32_t)__cvta_generic_to_shared(p);
}

// ------------------------- prep kernels ------------------------------------
__global__ void build_dct_kernel(){
  int idx = blockIdx.x*256 + threadIdx.x;
  int i = idx >> 10, j = idx & 1023;        // i = n, j = k
  const float c = 3.14159265358979323846f/2048.f;
  int m1 = ((2*i+1)*j) & 4095;
  g_MT[idx] = __float2half(2.f*cosf((float)m1 * c));
  float sc = (j==0) ? (0.5f/1024.f) : (1.f/1024.f);
  g_MinvA[idx] = __float2half(cosf((float)m1 * c) * sc);
}

__global__ void pack_conv_kernel(const float* __restrict__ w, __half* __restrict__ Bt){
  int idx = blockIdx.x*256 + threadIdx.x;
  int o = idx / 3072;
  int rem = idx - o*3072;
  int r = rem >> 10;
  int i = rem & 1023;
  Bt[idx] = __float2half(w[((o<<10) + i)*3 + r]);
}

__global__ void tcopy_kernel(const float* __restrict__ src, __half* __restrict__ dst,
                             int R, int C){
  __shared__ float t[32][33];
  int bx = blockIdx.x*32, by = blockIdx.y*32;
  int x = threadIdx.x, y = threadIdx.y;
  #pragma unroll
  for (int j=0;j<32;j+=8)
    t[y+j][x] = src[(size_t)(by+y+j)*C + bx + x];
  __syncthreads();
  #pragma unroll
  for (int j=0;j<32;j+=8)
    dst[(size_t)(bx+y+j)*R + by + x] = __float2half(t[x][y+j]);
}

__global__ void rcopy_kernel(const float* __restrict__ src, __half* __restrict__ dst){
  int idx = blockIdx.x*256 + threadIdx.x;
  float4 v = *(const float4*)(src + idx*4);
  __half2 h0 = __floats2half2_rn(v.x, v.y);
  __half2 h1 = __floats2half2_rn(v.z, v.w);
  *(uint2*)(dst + idx*4) = make_uint2(*(uint32_t*)&h0, *(uint32_t*)&h1);
}

// vt[bh][t][d] = v[bh][d][t]; grid (16,2,512), block (32,8)
__global__ void vtrans_kernel(const __half* __restrict__ v, __half* __restrict__ vt){
  __shared__ __half t[32][40];
  const int bh = blockIdx.z;
  const size_t base = (size_t)bh * 32768;
  const int t0 = blockIdx.x*32, d0 = blockIdx.y*32;
  const int x = threadIdx.x, y = threadIdx.y;
  #pragma unroll
  for (int j=0;j<32;j+=8)
    t[y+j][x] = v[base + (size_t)(d0+y+j)*512 + t0 + x];
  __syncthreads();
  #pragma unroll
  for (int j=0;j<32;j+=8)
    vt[base + (size_t)(t0+y+j)*64 + d0 + x] = t[x][y+j];
}

__global__ __launch_bounds__(256) void fold_bias_kernel(const float* __restrict__ b2){
  __shared__ float red[8];
  const int n = blockIdx.x, tid = threadIdx.x;
  const int lane = tid & 31, warp = tid >> 5;
  float s = 0.f;
  for (int k = tid; k < 1024; k += 256) s += b2[k]*__half2float(g_MinvA[(n<<10)+k]);
  #pragma unroll
  for (int o=16;o;o>>=1) s += __shfl_xor_sync(0xffffffffu,s,o);
  if (lane==0) red[warp]=s;
  __syncthreads();
  if (tid==0){
    float t=0.f;
    #pragma unroll
    for (int w2=0;w2<8;w2++) t+=red[w2];
    g_b2f[n]=t;
  }
}

// ------------------------- LayerNorm (f16 out) ------------------------------
__global__ __launch_bounds__(256) void ln_kernel(
    const float* __restrict__ x, const float* __restrict__ gw,
    const float* __restrict__ gb, __half* __restrict__ out)
{
  __shared__ float rs[8], rq[8], mv[2];
  const int row = blockIdx.x, tid = threadIdx.x;
  const int lane = tid & 31, warp = tid >> 5;
  const float4 xv = *(const float4*)(x + (size_t)row*1024 + tid*4);
  float s = xv.x+xv.y+xv.z+xv.w;
  float q = xv.x*xv.x+xv.y*xv.y+xv.z*xv.z+xv.w*xv.w;
  #pragma unroll
  for (int o=16;o;o>>=1){ s += __shfl_xor_sync(0xffffffffu,s,o); q += __shfl_xor_sync(0xffffffffu,q,o); }
  if (lane==0){ rs[warp]=s; rq[warp]=q; }
  __syncthreads();
  if (tid==0){
    float ss=0.f, qq=0.f;
    #pragma unroll
    for (int w2=0;w2<8;w2++){ ss+=rs[w2]; qq+=rq[w2]; }
    float m = ss*(1.f/1024.f);
    float var = qq*(1.f/1024.f) - m*m;
    mv[0]=m; mv[1]=rsqrtf(var + 1e-5f);
  }
  __syncthreads();
  const float m = mv[0], inv = mv[1];
  const float4 g4 = *(const float4*)(gw + tid*4);
  const float4 b4 = *(const float4*)(gb + tid*4);
  __half2 h0 = __floats2half2_rn((xv.x-m)*inv*g4.x + b4.x, (xv.y-m)*inv*g4.y + b4.y);
  __half2 h1 = __floats2half2_rn((xv.z-m)*inv*g4.z + b4.z, (xv.w-m)*inv*g4.w + b4.w);
  *(uint2*)(out + (size_t)row*1024 + tid*4) = make_uint2(*(uint32_t*)&h0, *(uint32_t*)&h1);
}

// ------------------------- fp16 GEMM: BK=64, 3-stage ring, interleaved ------
#define BM 128
#define BN 128
#define BK 64
#define STAGES 3
#define ASTRH 72
#define BTSTRH 72
#define AELE (BM*ASTRH)
#define BELE (BN*BTSTRH)
#define GEMM_SMEM_BYTES (STAGES*(AELE+BELE)*2)

__device__ __forceinline__ void gemm_load_stage(
    const __half* __restrict__ A, const __half* __restrict__ Bt,
    __half* asb, __half* bsb, int tid, int bm, int bn, int K, int lda,
    int conv, int kt)
{
  const int k0 = kt*BK;
  int roff = 0, kk0 = k0;
  if (conv){ roff = (k0 >> 10) - 1; kk0 = k0 & 1023; }
  #pragma unroll
  for (int j=0;j<4;j++){
    int i = tid + j*256;
    int ar = i >> 3, ac = (i & 7)*8;
    int grow = bm + ar;
    bool pr = true; int srow = grow;
    if (conv){
      int tt = grow & (TSEQ-1);
      int tp = tt + roff;
      pr = (tp >= 0) && (tp < TSEQ);
      srow = pr ? (grow + roff) : grow;
    }
    cp16(asb + ar*ASTRH + ac, A + (size_t)srow*lda + kk0 + ac, pr);
  }
  #pragma unroll
  for (int j=0;j<4;j++){
    int i = tid + j*256;
    int br = i >> 3, bc = (i & 7)*8;
    cp16(bsb + br*BTSTRH + bc, Bt + (size_t)(bn+br)*K + k0 + bc, true);
  }
  cp_commit();
}

__global__ __launch_bounds__(256) void gemm_kernel(
    const __half* __restrict__ A, const __half* __restrict__ Bt,
    const float* __restrict__ bias, const float* __restrict__ Rres,
    void* __restrict__ Cp, int M, int N, int K, int act, int conv, int ohalf)
{
  extern __shared__ __align__(16) __half sm[];
  __half* As = sm;
  __half* Bs = sm + STAGES*AELE;
  const int tid = threadIdx.x;
  const int bm = blockIdx.y*BM, bn = blockIdx.x*BN;
  const int lane = tid & 31, warp = tid >> 5;
  const int wm = warp >> 1, wn = warp & 1;
  const int rowW = wm*32, colW = wn*64;
  const int lda = conv ? DMODEL : K;
  const int KT = K / BK;

  // de-phase the two resident CTAs so one's LDSM burst overlaps the
  // other's MMA burst (output-invariant; pure delay).
  if ((blockIdx.x + blockIdx.y) & 1){
    long long t0c = clock64();
    while (clock64() - t0c < 900) {}
  }

  const uint32_t As32 = s2u32(As);
  const uint32_t Bs32 = s2u32(Bs);
  uint32_t aoffm[2];
  #pragma unroll
  for (int mt=0; mt<2; mt++)
    aoffm[mt] = (uint32_t)(((rowW + mt*16 + (lane & 15))*ASTRH + ((lane >> 4)*8))*2);
  uint32_t boffp[4];
  #pragma unroll
  for (int p=0; p<4; p++)
    boffp[p] = (uint32_t)(((colW + p*16 + (lane & 7) + ((lane >> 4)*8))*BTSTRH
                          + (((lane >> 3) & 1)*8))*2);

  float acc[2][8][4];
  #pragma unroll
  for (int a1=0;a1<2;a1++)
    #pragma unroll
    for (int a2=0;a2<8;a2++)
      #pragma unroll
      for (int a3=0;a3<4;a3++) acc[a1][a2][a3]=0.f;

  #pragma unroll
  for (int s=0; s<STAGES-1; s++){
    if (s < KT)
      gemm_load_stage(A,Bt,As+s*AELE,Bs+s*BELE,tid,bm,bn,K,lda,conv,s);
    else
      cp_commit();
  }

  for (int kt=0; kt<KT; kt++){
    const int cur = kt % STAGES;
    cp_wait<STAGES-2>();
    __syncthreads();
    const int nxt = kt + STAGES - 1;
    if (nxt < KT)
      gemm_load_stage(A,Bt,As+(nxt%STAGES)*AELE,Bs+(nxt%STAGES)*BELE,
                      tid,bm,bn,K,lda,conv,nxt);
    else
      cp_commit();

    const uint32_t ab = As32 + (uint32_t)(cur*AELE*2);
    const uint32_t bb = Bs32 + (uint32_t)(cur*BELE*2);

    uint32_t af[2][4], bfl[4][2], bfh[4][2];
    // preload ks=0: A frags + B low half (nt 0..3)
    LDSM4(af[0][0], af[0][1], af[0][2], af[0][3], ab + aoffm[0]);
    LDSM4(af[1][0], af[1][1], af[1][2], af[1][3], ab + aoffm[1]);
    LDSM4(bfl[0][0], bfl[0][1], bfl[1][0], bfl[1][1], bb + boffp[0]);
    LDSM4(bfl[2][0], bfl[2][1], bfl[3][0], bfl[3][1], bb + boffp[1]);

    #pragma unroll
    for (int ks=0; ks<4; ks++){
      const uint32_t kb = (uint32_t)(ks*32);
      const uint32_t kn = kb + 32;
      // load B high half for current ks
      LDSM4(bfh[0][0], bfh[0][1], bfh[1][0], bfh[1][1], bb + boffp[2] + kb);
      LDSM4(bfh[2][0], bfh[2][1], bfh[3][0], bfh[3][1], bb + boffp[3] + kb);
      // MMA low half (nt 0..3)
      #pragma unroll
      for (int mt=0; mt<2; mt++)
        #pragma unroll
        for (int nt=0; nt<4; nt++)
          mma16(acc[mt][nt], af[mt], bfl[nt]);
      // load B low half for next ks (bfl dead after MMA-low)
      if (ks < 3){
        LDSM4(bfl[0][0], bfl[0][1], bfl[1][0], bfl[1][1], bb + boffp[0] + kn);
        LDSM4(bfl[2][0], bfl[2][1], bfl[3][0], bfl[3][1], bb + boffp[1] + kn);
      }
      // MMA high half (nt 4..7)
      #pragma unroll
      for (int mt=0; mt<2; mt++)
        #pragma unroll
        for (int nt=0; nt<4; nt++)
          mma16(acc[mt][nt+4], af[mt], bfh[nt]);
      // load A for next ks (af dead after MMA-high)
      if (ks < 3){
        LDSM4(af[0][0], af[0][1], af[0][2], af[0][3], ab + aoffm[0] + kn);
        LDSM4(af[1][0], af[1][1], af[1][2], af[1][3], ab + aoffm[1] + kn);
      }
    }
  }

  float* Cf = (float*)Cp;
  __half* Ch = (__half*)Cp;
  #pragma unroll
  for (int mt=0; mt<2; mt++){
    const int r0 = bm + rowW + mt*16 + (lane>>2);
    #pragma unroll
    for (int nt=0; nt<8; nt++){
      const int c0 = bn + colW + nt*8 + (lane&3)*2;
      const float bb0 = bias ? bias[c0]   : 0.f;
      const float bb1 = bias ? bias[c0+1] : 0.f;
      #pragma unroll
      for (int rr=0; rr<2; rr++){
        const int r = r0 + rr*8;
        float v0 = acc[mt][nt][rr*2+0] + bb0;
        float v1 = acc[mt][nt][rr*2+1] + bb1;
        if (act==1){ v0 = gelu_f(v0); v1 = gelu_f(v1); }
        else if (act==2){ v0 = silu_f(v0); v1 = silu_f(v1); }
        if (Rres){
          const float* rp = Rres + (size_t)r*N + c0;
          v0 += rp[0]; v1 += rp[1];
        }
        if (ohalf){
          __half2 h = __floats2half2_rn(v0, v1);
          *(__half2*)(Ch + (size_t)r*N + c0) = h;
        } else {
          *(float2*)(Cf + (size_t)r*N + c0) = make_float2(v0, v1);
        }
      }
    }
  }
}

// ------------------------- channel attention (tensor-core) ------------------
__global__ __launch_bounds__(256) void attn_kernel(
    const __half* __restrict__ qh, const __half* __restrict__ kh,
    const __half* __restrict__ vt, const float* __restrict__ temp,
    const float* __restrict__ x, float* __restrict__ y)
{
  __shared__ float  Ps[64*65];
  __shared__ __half Ph[64*72];
  __shared__ __half Buf[128*72];
  const int bh = blockIdx.x;
  const int h = bh & 15;
  const size_t base = (size_t)bh * 32768;
  const int tid = threadIdx.x;
  const int lane = tid & 31, w = tid >> 5;
  __half* Qs = Buf;            // 64 x 72
  __half* Ks = Buf + 64*72;    // 64 x 72
  const uint32_t Qs32 = s2u32(Qs), Ks32 = s2u32(Ks);
  const uint32_t Ph32 = s2u32(Ph), Bf32 = s2u32(Buf);

  const int mrow = (w & 3) * 16;

  // ---- phase 1: S = Q K^T (f32 accum), warp tile 16x32 ----
  const int nb1 = (w >> 2) * 32;
  const uint32_t aoff = (uint32_t)(((mrow + (lane & 15))*72 + ((lane >> 4)*8))*2);
  uint32_t boff1[2];
  #pragma unroll
  for (int nt=0; nt<2; nt++)
    boff1[nt] = (uint32_t)(((nb1 + nt*16 + (lane & 7) + ((lane >> 4)*8))*72
                           + (((lane >> 3) & 1)*8))*2);

  float acc1[4][4];
  #pragma unroll
  for (int i=0;i<4;i++)
    #pragma unroll
    for (int j=0;j<4;j++) acc1[i][j]=0.f;

  const int lr = tid >> 2, lc = (tid & 3)*16;   // chunk loader: row 0..63, 16 cols
  for (int c = 0; c < 8; c++){
    const size_t gq = base + (size_t)lr*512 + c*64 + lc;
    *(uint4*)(Qs + lr*72 + lc)     = *(const uint4*)(qh + gq);
    *(uint4*)(Qs + lr*72 + lc + 8) = *(const uint4*)(qh + gq + 8);
    *(uint4*)(Ks + lr*72 + lc)     = *(const uint4*)(kh + gq);
    *(uint4*)(Ks + lr*72 + lc + 8) = *(const uint4*)(kh + gq + 8);
    __syncthreads();
    #pragma unroll
    for (int ks=0; ks<4; ks++){
      uint32_t a[4], bf[2][4];
      LDSM4(a[0], a[1], a[2], a[3], Qs32 + aoff + ks*32);
      #pragma unroll
      for (int nt=0; nt<2; nt++){
        LDSM4(bf[nt][0], bf[nt][1], bf[nt][2], bf[nt][3], Ks32 + boff1[nt] + ks*32);
        mma16(acc1[nt*2+0], a, &bf[nt][0]);
        mma16(acc1[nt*2+1], a, &bf[nt][2]);
      }
    }
    __syncthreads();
  }
  const float tmp = temp[h];
  #pragma unroll
  for (int nt=0; nt<4; nt++){
    const int col = nb1 + nt*8 + (lane & 3)*2;
    const int r0 = mrow + (lane >> 2);
    Ps[r0*65 + col]       = acc1[nt][0]*tmp;
    Ps[r0*65 + col + 1]   = acc1[nt][1]*tmp;
    Ps[(r0+8)*65 + col]   = acc1[nt][2]*tmp;
    Ps[(r0+8)*65 + col+1] = acc1[nt][3]*tmp;
  }
  __syncthreads();

  // ---- phase 2: softmax rows, P -> fp16 ----
  if (tid < 64){
    float* row = Ps + tid*65;
    float m = row[0];
    #pragma unroll 8
    for (int e=1;e<64;e++) m = fmaxf(m, row[e]);
    float s = 0.f;
    #pragma unroll 8
    for (int e=0;e<64;e++){ float ev = expf(row[e]-m); row[e]=ev; s+=ev; }
    float inv = 1.f/s;
    __half* pr = Ph + tid*72;
    #pragma unroll 8
    for (int e=0;e<64;e++) pr[e] = __float2half(row[e]*inv);
  }
  __syncthreads();

  // ---- phase 3: O = P @ Vt^T, warp tile 16x64, 4 chunks of 128 t-cols ----
  const int nb3 = (w >> 2) * 64;
  uint32_t boff3[4];
  #pragma unroll
  for (int nt=0; nt<4; nt++)
    boff3[nt] = (uint32_t)(((nb3 + nt*16 + (lane & 7) + ((lane >> 4)*8))*72
                           + (((lane >> 3) & 1)*8))*2);
  const int vr = tid >> 1, vc = (tid & 1)*32;   // Vt loader: 128 rows x 64 cols

  for (int nc = 0; nc < 4; nc++){
    const int t0 = nc*128;
    const size_t gv = base + (size_t)(t0 + vr)*64 + vc;
    *(uint4*)(Buf + vr*72 + vc)      = *(const uint4*)(vt + gv);
    *(uint4*)(Buf + vr*72 + vc + 8)  = *(const uint4*)(vt + gv + 8);
    *(uint4*)(Buf + vr*72 + vc + 16) = *(const uint4*)(vt + gv + 16);
    *(uint4*)(Buf + vr*72 + vc + 24) = *(const uint4*)(vt + gv + 24);
    __syncthreads();

    float acc2[8][4];
    #pragma unroll
    for (int i=0;i<8;i++)
      #pragma unroll
      for (int j=0;j<4;j++) acc2[i][j]=0.f;

    #pragma unroll
    for (int ks=0; ks<4; ks++){
      uint32_t a[4], bf[4][4];
      LDSM4(a[0], a[1], a[2], a[3], Ph32 + aoff + ks*32);
      #pragma unroll
      for (int nt=0; nt<4; nt++){
        LDSM4(bf[nt][0], bf[nt][1], bf[nt][2], bf[nt][3], Bf32 + boff3[nt] + ks*32);
        mma16(acc2[nt*2+0], a, &bf[nt][0]);
        mma16(acc2[nt*2+1], a, &bf[nt][2]);
      }
    }

    #pragma unroll
    for (int nt=0; nt<8; nt++){
      const int t = t0 + nb3 + nt*8 + (lane & 3)*2;
      const int d0 = mrow + (lane >> 2);
      #pragma unroll
      for (int rr=0; rr<2; rr++){
        const int d = d0 + rr*8;
        const size_t o = base + (size_t)d*512 + t;
        y[o]   = acc2[nt][rr*2+0] + x[o];
        y[o+1] = acc2[nt][rr*2+1] + x[o+1];
      }
    }
    __syncthreads();
  }
}

// ------------------------- launch ------------------------------------------
static void launch_gemm(const __half* A, const __half* Bt, const float* bias,
                        const float* R, void* C, int M, int N, int K,
                        int act, int conv, int ohalf){
  dim3 grid(N/BN, M/BM);
  gemm_kernel<<<grid, 256, GEMM_SMEM_BYTES>>>(A, Bt, bias, R, C, M, N, K, act, conv, ohalf);
}
static void launch_tcopy(const float* src, __half* dst, int R, int C){
  dim3 grid(C/32, R/32), block(32,8);
  tcopy_kernel<<<grid, block>>>(src, dst, R, C);
}

extern "C" void kernel_launch(void* const* d_in, const int* in_sizes, int n_in,
                              void* d_out, int out_size) {
  const float* x       = (const float*)d_in[0];
  const float* q_w     = (const float*)d_in[1];
  const float* q_b     = (const float*)d_in[2];
  const float* k_w     = (const float*)d_in[3];
  const float* k_b     = (const float*)d_in[4];
  const float* v_w     = (const float*)d_in[5];
  const float* v_b     = (const float*)d_in[6];
  const float* temp    = (const float*)d_in[7];
  const float* ln1_w   = (const float*)d_in[8];
  const float* ln1_b   = (const float*)d_in[9];
  const float* ln2_w   = (const float*)d_in[10];
  const float* ln2_b   = (const float*)d_in[11];
  const float* ln3_w   = (const float*)d_in[12];
  const float* ln3_b   = (const float*)d_in[13];
  const float* ln4_w   = (const float*)d_in[14];
  const float* ln4_b   = (const float*)d_in[15];
  const float* lin1_w  = (const float*)d_in[16];
  const float* lin1_b  = (const float*)d_in[17];
  const float* lin2_w  = (const float*)d_in[18];
  const float* lin2_b  = (const float*)d_in[19];
  const float* mlp1_w1 = (const float*)d_in[20];
  const float* mlp1_b1 = (const float*)d_in[21];
  const float* mlp1_w2 = (const float*)d_in[22];
  const float* mlp1_b2 = (const float*)d_in[23];
  const float* mlp2_w1 = (const float*)d_in[24];
  const float* mlp2_b1 = (const float*)d_in[25];
  const float* mlp2_w2 = (const float*)d_in[26];
  const float* mlp2_b2 = (const float*)d_in[27];
  const float* conv1_w = (const float*)d_in[28];
  const float* conv1_b = (const float*)d_in[29];
  const float* conv2_w = (const float*)d_in[30];
  const float* conv2_b = (const float*)d_in[31];
  float* out = (float*)d_out;

  cudaFuncSetAttribute(gemm_kernel, cudaFuncAttributeMaxDynamicSharedMemorySize, GEMM_SMEM_BYTES);

  __half *p_ln, *p_wide, *p_dy, *p_c1, *p_qh, *p_kh, *p_vh, *p_vt;
  float  *p_y, *p_y2, *p_b2f;
  __half *p_MT, *p_MinvA, *p_W1fT, *p_W2fT, *p_Bc1t, *p_Bc2t;
  __half *p_qwt, *p_kwt, *p_vwt, *p_lin1t, *p_lin2r, *p_m11t, *p_m12t, *p_m21t, *p_m22t;
  cudaGetSymbolAddress((void**)&p_ln,   g_ln);
  cudaGetSymbolAddress((void**)&p_wide, g_wide);
  cudaGetSymbolAddress((void**)&p_dy,   g_dy);
  cudaGetSymbolAddress((void**)&p_c1,   g_c1);
  cudaGetSymbolAddress((void**)&p_qh,   g_qh);
  cudaGetSymbolAddress((void**)&p_kh,   g_kh);
  cudaGetSymbolAddress((void**)&p_vh,   g_vh);
  cudaGetSymbolAddress((void**)&p_vt,   g_vt);
  cudaGetSymbolAddress((void**)&p_y,    g_y);
  cudaGetSymbolAddress((void**)&p_y2,   g_y2);
  cudaGetSymbolAddress((void**)&p_b2f,  g_b2f);
  cudaGetSymbolAddress((void**)&p_MT,   g_MT);
  cudaGetSymbolAddress((void**)&p_MinvA,g_MinvA);
  cudaGetSymbolAddress((void**)&p_W1fT, g_W1fT);
  cudaGetSymbolAddress((void**)&p_W2fT, g_W2fT);
  cudaGetSymbolAddress((void**)&p_Bc1t, g_Bc1t);
  cudaGetSymbolAddress((void**)&p_Bc2t, g_Bc2t);
  cudaGetSymbolAddress((void**)&p_qwt,  g_qwt);
  cudaGetSymbolAddress((void**)&p_kwt,  g_kwt);
  cudaGetSymbolAddress((void**)&p_vwt,  g_vwt);
  cudaGetSymbolAddress((void**)&p_lin1t,g_lin1t);
  cudaGetSymbolAddress((void**)&p_lin2r,g_lin2r);
  cudaGetSymbolAddress((void**)&p_m11t, g_m11t);
  cudaGetSymbolAddress((void**)&p_m12t, g_m12t);
  cudaGetSymbolAddress((void**)&p_m21t, g_m21t);
  cudaGetSymbolAddress((void**)&p_m22t, g_m22t);

  // attention block; launch index 3 = Q-projection GEMM (profiling target)
  ln_kernel<<<TOK, 256>>>(x, ln1_w, ln1_b, p_ln);                               // 0
  launch_tcopy(q_w, p_qwt, DMODEL, DMODEL);                                     // 1
  launch_tcopy(k_w, p_kwt, DMODEL, DMODEL);                                     // 2
  launch_gemm(p_ln, p_qwt, q_b, nullptr, p_qh, TOK, DMODEL, DMODEL, 0, 0, 1);   // 3
  launch_tcopy(v_w, p_vwt, DMODEL, DMODEL);                                     // 4
  launch_gemm(p_ln, p_kwt, k_b, nullptr, p_kh, TOK, DMODEL, DMODEL, 0, 0, 1);
  launch_gemm(p_ln, p_vwt, v_b, nullptr, p_vh, TOK, DMODEL, DMODEL, 0, 0, 1);
  vtrans_kernel<<<dim3(16,2,512), dim3(32,8)>>>(p_vh, p_vt);
  attn_kernel<<<512, 256>>>(p_qh, p_kh, p_vt, temp, x, p_y);

  // prep: DCT folds + weight transposes + conv packs
  build_dct_kernel<<<4096, 256>>>();
  launch_tcopy(lin1_w, p_lin1t, DMODEL, DFF);
  rcopy_kernel<<<(DFF*DMODEL)/1024, 256>>>(lin2_w, p_lin2r);
  launch_tcopy(mlp1_w1, p_m11t, DMODEL, DFF);
  launch_tcopy(mlp1_w2, p_m12t, DFF, DMODEL);
  launch_tcopy(mlp2_w1, p_m21t, DMODEL, DFF);
  launch_tcopy(mlp2_w2, p_m22t, DFF, DMODEL);
  pack_conv_kernel<<<12288, 256>>>(conv1_w, p_Bc1t);
  pack_conv_kernel<<<12288, 256>>>(conv2_w, p_Bc2t);
  launch_gemm(p_lin1t, p_MT,    nullptr, nullptr, p_W1fT, DFF,    DMODEL, DMODEL, 0, 0, 1);
  launch_gemm(p_MinvA, p_lin2r, nullptr, nullptr, p_W2fT, DMODEL, DFF,    DMODEL, 0, 0, 1);
  fold_bias_kernel<<<DMODEL, 256>>>(lin2_b);

  // DCT-folded MLP
  ln_kernel<<<TOK, 256>>>(p_y, ln2_w, ln2_b, p_ln);
  launch_gemm(p_ln,   p_W1fT, lin1_b, nullptr, p_wide, TOK, DFF,    DMODEL, 1, 0, 1);
  launch_gemm(p_wide, p_W2fT, p_b2f,  nullptr, p_dy,   TOK, DMODEL, DFF,    0, 0, 1);

  // mlp1(d_y) + y
  launch_gemm(p_dy,   p_m11t, mlp1_b1, nullptr, p_wide, TOK, DFF,    DMODEL, 1, 0, 1);
  launch_gemm(p_wide, p_m12t, mlp1_b2, p_y,     p_y2,   TOK, DMODEL, DFF,    0, 0, 0);

  // mlp2(ln3(y)) added
  ln_kernel<<<TOK, 256>>>(p_y, ln3_w, ln3_b, p_ln);
  launch_gemm(p_ln,   p_m21t, mlp2_b1, nullptr, p_wide, TOK, DFF,    DMODEL, 1, 0, 1);
  launch_gemm(p_wide, p_m22t, mlp2_b2, p_y2,    p_y2,   TOK, DMODEL, DFF,    0, 0, 0);

  // conv path (shifted GEMMs, K=3072), silu between; final residual y2
  ln_kernel<<<TOK, 256>>>(p_y2, ln4_w, ln4_b, p_ln);
  launch_gemm(p_ln, p_Bc1t, conv1_b, nullptr, p_c1, TOK, DMODEL, 3*DMODEL, 2, 1, 1);
  launch_gemm(p_c1, p_Bc2t, conv2_b, p_y2,    out,  TOK, DMODEL, 3*DMODEL, 0, 1, 0);
}

// round 17
// speedup vs baseline: 1.3242x; 1.3242x over previous
#include <cuda_runtime.h>
#include <cuda_fp16.h>
#include <math.h>
#include <stdint.h>

#define TOK    16384
#define DMODEL 1024
#define DFF    2048
#define TSEQ   512
#define TDSZ   (TSEQ*DMODEL)

// ------------------------- scratch (device globals; no allocs) -------------
__device__ __half g_ln  [TOK*DMODEL];
__device__ __half g_wide[TOK*DFF];
__device__ __half g_dy  [TOK*DMODEL];
__device__ __half g_c1  [TOK*DMODEL];
__device__ __half g_qh  [TOK*DMODEL];
__device__ __half g_kh  [TOK*DMODEL];
__device__ __half g_vh  [TOK*DMODEL];
__device__ __half g_vt  [TOK*DMODEL];
__device__ float  g_y   [TOK*DMODEL];
__device__ float  g_y2  [TOK*DMODEL];
__device__ __half g_MT   [DMODEL*DMODEL];
__device__ __half g_MinvA[DMODEL*DMODEL];
__device__ __half g_W1fT [DFF*DMODEL];
__device__ __half g_W2fT [DMODEL*DFF];
__device__ float  g_b2f  [DMODEL];
__device__ __half g_Bc1t [DMODEL*3*DMODEL];
__device__ __half g_Bc2t [DMODEL*3*DMODEL];
__device__ __half g_qwt  [DMODEL*DMODEL];
__device__ __half g_kwt  [DMODEL*DMODEL];
__device__ __half g_vwt  [DMODEL*DMODEL];
__device__ __half g_lin1t[DFF*DMODEL];
__device__ __half g_lin2r[DFF*DMODEL];
__device__ __half g_m11t [DFF*DMODEL];
__device__ __half g_m12t [DMODEL*DFF];
__device__ __half g_m21t [DFF*DMODEL];
__device__ __half g_m22t [DMODEL*DFF];

// ------------------------- helpers ----------------------------------------
__device__ __forceinline__ void mma16(float* d, const uint32_t* a, const uint32_t* b){
  asm volatile(
    "mma.sync.aligned.m16n8k16.row.col.f32.f16.f16.f32 "
    "{%0,%1,%2,%3}, {%4,%5,%6,%7}, {%8,%9}, {%0,%1,%2,%3};"
    : "+f"(d[0]), "+f"(d[1]), "+f"(d[2]), "+f"(d[3])
    : "r"(a[0]), "r"(a[1]), "r"(a[2]), "r"(a[3]), "r"(b[0]), "r"(b[1]));
}
#define LDSM4(r0,r1,r2,r3,addr) \
  asm volatile("ldmatrix.sync.aligned.m8n8.x4.shared.b16 {%0,%1,%2,%3}, [%4];" \
               : "=r"(r0), "=r"(r1), "=r"(r2), "=r"(r3) : "r"(addr))
__device__ __forceinline__ void cp16(void* sdst, const void* gsrc, bool pred){
  uint32_t s = (uint32_t)__cvta_generic_to_shared(sdst);
  int n = pred ? 16 : 0;
  asm volatile("cp.async.cg.shared.global [%0], [%1], 16, %2;" :: "r"(s), "l"(gsrc), "r"(n));
}
__device__ __forceinline__ void cp_commit(){ asm volatile("cp.async.commit_group;"); }
template<int N> __device__ __forceinline__ void cp_wait(){
  asm volatile("cp.async.wait_group %0;" :: "n"(N));
}
__device__ __forceinline__ float gelu_f(float x){
  return 0.5f*x*(1.f + erff(x*0.70710678118654752f));
}
__device__ __forceinline__ float silu_f(float x){ return x/(1.f+expf(-x)); }
__device__ __forceinline__ uint32_t s2u32(const void* p){
  return (uint32_t)__cvta_generic_to_shared(p);
}

// ------------------------- prep kernels ------------------------------------
__global__ void build_dct_kernel(){
  int idx = blockIdx.x*256 + threadIdx.x;
  int i = idx >> 10, j = idx & 1023;        // i = n, j = k
  const float c = 3.14159265358979323846f/2048.f;
  int m1 = ((2*i+1)*j) & 4095;
  g_MT[idx] = __float2half(2.f*cosf((float)m1 * c));
  float sc = (j==0) ? (0.5f/1024.f) : (1.f/1024.f);
  g_MinvA[idx] = __float2half(cosf((float)m1 * c) * sc);
}

__global__ void pack_conv_kernel(const float* __restrict__ w, __half* __restrict__ Bt){
  int idx = blockIdx.x*256 + threadIdx.x;
  int o = idx / 3072;
  int rem = idx - o*3072;
  int r = rem >> 10;
  int i = rem & 1023;
  Bt[idx] = __float2half(w[((o<<10) + i)*3 + r]);
}

__global__ void tcopy_kernel(const float* __restrict__ src, __half* __restrict__ dst,
                             int R, int C){
  __shared__ float t[32][33];
  int bx = blockIdx.x*32, by = blockIdx.y*32;
  int x = threadIdx.x, y = threadIdx.y;
  #pragma unroll
  for (int j=0;j<32;j+=8)
    t[y+j][x] = src[(size_t)(by+y+j)*C + bx + x];
  __syncthreads();
  #pragma unroll
  for (int j=0;j<32;j+=8)
    dst[(size_t)(bx+y+j)*R + by + x] = __float2half(t[x][y+j]);
}

__global__ void rcopy_kernel(const float* __restrict__ src, __half* __restrict__ dst){
  int idx = blockIdx.x*256 + threadIdx.x;
  float4 v = *(const float4*)(src + idx*4);
  __half2 h0 = __floats2half2_rn(v.x, v.y);
  __half2 h1 = __floats2half2_rn(v.z, v.w);
  *(uint2*)(dst + idx*4) = make_uint2(*(uint32_t*)&h0, *(uint32_t*)&h1);
}

// vt[bh][t][d] = v[bh][d][t]; grid (16,2,512), block (32,8)
__global__ void vtrans_kernel(const __half* __restrict__ v, __half* __restrict__ vt){
  __shared__ __half t[32][40];
  const int bh = blockIdx.z;
  const size_t base = (size_t)bh * 32768;
  const int t0 = blockIdx.x*32, d0 = blockIdx.y*32;
  const int x = threadIdx.x, y = threadIdx.y;
  #pragma unroll
  for (int j=0;j<32;j+=8)
    t[y+j][x] = v[base + (size_t)(d0+y+j)*512 + t0 + x];
  __syncthreads();
  #pragma unroll
  for (int j=0;j<32;j+=8)
    vt[base + (size_t)(t0+y+j)*64 + d0 + x] = t[x][y+j];
}

__global__ __launch_bounds__(256) void fold_bias_kernel(const float* __restrict__ b2){
  __shared__ float red[8];
  const int n = blockIdx.x, tid = threadIdx.x;
  const int lane = tid & 31, warp = tid >> 5;
  float s = 0.f;
  for (int k = tid; k < 1024; k += 256) s += b2[k]*__half2float(g_MinvA[(n<<10)+k]);
  #pragma unroll
  for (int o=16;o;o>>=1) s += __shfl_xor_sync(0xffffffffu,s,o);
  if (lane==0) red[warp]=s;
  __syncthreads();
  if (tid==0){
    float t=0.f;
    #pragma unroll
    for (int w2=0;w2<8;w2++) t+=red[w2];
    g_b2f[n]=t;
  }
}

// ------------------------- LayerNorm (f16 out) ------------------------------
__global__ __launch_bounds__(256) void ln_kernel(
    const float* __restrict__ x, const float* __restrict__ gw,
    const float* __restrict__ gb, __half* __restrict__ out)
{
  __shared__ float rs[8], rq[8], mv[2];
  const int row = blockIdx.x, tid = threadIdx.x;
  const int lane = tid & 31, warp = tid >> 5;
  const float4 xv = *(const float4*)(x + (size_t)row*1024 + tid*4);
  float s = xv.x+xv.y+xv.z+xv.w;
  float q = xv.x*xv.x+xv.y*xv.y+xv.z*xv.z+xv.w*xv.w;
  #pragma unroll
  for (int o=16;o;o>>=1){ s += __shfl_xor_sync(0xffffffffu,s,o); q += __shfl_xor_sync(0xffffffffu,q,o); }
  if (lane==0){ rs[warp]=s; rq[warp]=q; }
  __syncthreads();
  if (tid==0){
    float ss=0.f, qq=0.f;
    #pragma unroll
    for (int w2=0;w2<8;w2++){ ss+=rs[w2]; qq+=rq[w2]; }
    float m = ss*(1.f/1024.f);
    float var = qq*(1.f/1024.f) - m*m;
    mv[0]=m; mv[1]=rsqrtf(var + 1e-5f);
  }
  __syncthreads();
  const float m = mv[0], inv = mv[1];
  const float4 g4 = *(const float4*)(gw + tid*4);
  const float4 b4 = *(const float4*)(gb + tid*4);
  __half2 h0 = __floats2half2_rn((xv.x-m)*inv*g4.x + b4.x, (xv.y-m)*inv*g4.y + b4.y);
  __half2 h1 = __floats2half2_rn((xv.z-m)*inv*g4.z + b4.z, (xv.w-m)*inv*g4.w + b4.w);
  *(uint2*)(out + (size_t)row*1024 + tid*4) = make_uint2(*(uint32_t*)&h0, *(uint32_t*)&h1);
}

// ------------------------- fp16 GEMM: BK=64, 3-stage ring, interleaved ------
#define BM 128
#define BN 128
#define BK 64
#define STAGES 3
#define ASTRH 72
#define BTSTRH 72
#define AELE (BM*ASTRH)
#define BELE (BN*BTSTRH)
#define GEMM_SMEM_BYTES (STAGES*(AELE+BELE)*2)

__device__ __forceinline__ void gemm_load_stage(
    const __half* __restrict__ A, const __half* __restrict__ Bt,
    __half* asb, __half* bsb, int tid, int bm, int bn, int K, int lda,
    int conv, int kt)
{
  const int k0 = kt*BK;
  int roff = 0, kk0 = k0;
  if (conv){ roff = (k0 >> 10) - 1; kk0 = k0 & 1023; }
  #pragma unroll
  for (int j=0;j<4;j++){
    int i = tid + j*256;
    int ar = i >> 3, ac = (i & 7)*8;
    int grow = bm + ar;
    bool pr = true; int srow = grow;
    if (conv){
      int tt = grow & (TSEQ-1);
      int tp = tt + roff;
      pr = (tp >= 0) && (tp < TSEQ);
      srow = pr ? (grow + roff) : grow;
    }
    cp16(asb + ar*ASTRH + ac, A + (size_t)srow*lda + kk0 + ac, pr);
  }
  #pragma unroll
  for (int j=0;j<4;j++){
    int i = tid + j*256;
    int br = i >> 3, bc = (i & 7)*8;
    cp16(bsb + br*BTSTRH + bc, Bt + (size_t)(bn+br)*K + k0 + bc, true);
  }
  cp_commit();
}

__global__ __launch_bounds__(256, 2) void gemm_kernel(
    const __half* __restrict__ A, const __half* __restrict__ Bt,
    const float* __restrict__ bias, const float* __restrict__ Rres,
    void* __restrict__ Cp, int M, int N, int K, int act, int conv, int ohalf)
{
  extern __shared__ __align__(16) __half sm[];
  __half* As = sm;
  __half* Bs = sm + STAGES*AELE;
  const int tid = threadIdx.x;
  const int bm = blockIdx.y*BM, bn = blockIdx.x*BN;
  const int lane = tid & 31, warp = tid >> 5;
  const int wm = warp >> 1, wn = warp & 1;
  const int rowW = wm*32, colW = wn*64;
  const int lda = conv ? DMODEL : K;
  const int KT = K / BK;

  const uint32_t As32 = s2u32(As);
  const uint32_t Bs32 = s2u32(Bs);
  uint32_t aoffm[2];
  #pragma unroll
  for (int mt=0; mt<2; mt++)
    aoffm[mt] = (uint32_t)(((rowW + mt*16 + (lane & 15))*ASTRH + ((lane >> 4)*8))*2);
  uint32_t boffp[4];
  #pragma unroll
  for (int p=0; p<4; p++)
    boffp[p] = (uint32_t)(((colW + p*16 + (lane & 7) + ((lane >> 4)*8))*BTSTRH
                          + (((lane >> 3) & 1)*8))*2);

  float acc[2][8][4];
  #pragma unroll
  for (int a1=0;a1<2;a1++)
    #pragma unroll
    for (int a2=0;a2<8;a2++)
      #pragma unroll
      for (int a3=0;a3<4;a3++) acc[a1][a2][a3]=0.f;

  #pragma unroll
  for (int s=0; s<STAGES-1; s++){
    if (s < KT)
      gemm_load_stage(A,Bt,As+s*AELE,Bs+s*BELE,tid,bm,bn,K,lda,conv,s);
    else
      cp_commit();
  }

  for (int kt=0; kt<KT; kt++){
    const int cur = kt % STAGES;
    cp_wait<STAGES-2>();
    __syncthreads();
    const int nxt = kt + STAGES - 1;
    if (nxt < KT)
      gemm_load_stage(A,Bt,As+(nxt%STAGES)*AELE,Bs+(nxt%STAGES)*BELE,
                      tid,bm,bn,K,lda,conv,nxt);
    else
      cp_commit();

    const uint32_t ab = As32 + (uint32_t)(cur*AELE*2);
    const uint32_t bb = Bs32 + (uint32_t)(cur*BELE*2);

    uint32_t af[2][4], bfl[4][2], bfh[4][2];
    // preload ks=0: A frags + B low half (nt 0..3)
    LDSM4(af[0][0], af[0][1], af[0][2], af[0][3], ab + aoffm[0]);
    LDSM4(af[1][0], af[1][1], af[1][2], af[1][3], ab + aoffm[1]);
    LDSM4(bfl[0][0], bfl[0][1], bfl[1][0], bfl[1][1], bb + boffp[0]);
    LDSM4(bfl[2][0], bfl[2][1], bfl[3][0], bfl[3][1], bb + boffp[1]);

    #pragma unroll
    for (int ks=0; ks<4; ks++){
      const uint32_t kb = (uint32_t)(ks*32);
      const uint32_t kn = kb + 32;
      // load B high half for current ks
      LDSM4(bfh[0][0], bfh[0][1], bfh[1][0], bfh[1][1], bb + boffp[2] + kb);
      LDSM4(bfh[2][0], bfh[2][1], bfh[3][0], bfh[3][1], bb + boffp[3] + kb);
      // MMA low half (nt 0..3)
      #pragma unroll
      for (int mt=0; mt<2; mt++)
        #pragma unroll
        for (int nt=0; nt<4; nt++)
          mma16(acc[mt][nt], af[mt], bfl[nt]);
      // load B low half for next ks (bfl dead after MMA-low)
      if (ks < 3){
        LDSM4(bfl[0][0], bfl[0][1], bfl[1][0], bfl[1][1], bb + boffp[0] + kn);
        LDSM4(bfl[2][0], bfl[2][1], bfl[3][0], bfl[3][1], bb + boffp[1] + kn);
      }
      // MMA high half (nt 4..7)
      #pragma unroll
      for (int mt=0; mt<2; mt++)
        #pragma unroll
        for (int nt=0; nt<4; nt++)
          mma16(acc[mt][nt+4], af[mt], bfh[nt]);
      // load A for next ks (af dead after MMA-high)
      if (ks < 3){
        LDSM4(af[0][0], af[0][1], af[0][2], af[0][3], ab + aoffm[0] + kn);
        LDSM4(af[1][0], af[1][1], af[1][2], af[1][3], ab + aoffm[1] + kn);
      }
    }
  }

  float* Cf = (float*)Cp;
  __half* Ch = (__half*)Cp;
  #pragma unroll
  for (int mt=0; mt<2; mt++){
    const int r0 = bm + rowW + mt*16 + (lane>>2);
    #pragma unroll
    for (int nt=0; nt<8; nt++){
      const int c0 = bn + colW + nt*8 + (lane&3)*2;
      const float bb0 = bias ? bias[c0]   : 0.f;
      const float bb1 = bias ? bias[c0+1] : 0.f;
      #pragma unroll
      for (int rr=0; rr<2; rr++){
        const int r = r0 + rr*8;
        float v0 = acc[mt][nt][rr*2+0] + bb0;
        float v1 = acc[mt][nt][rr*2+1] + bb1;
        if (act==1){ v0 = gelu_f(v0); v1 = gelu_f(v1); }
        else if (act==2){ v0 = silu_f(v0); v1 = silu_f(v1); }
        if (Rres){
          const float* rp = Rres + (size_t)r*N + c0;
          v0 += rp[0]; v1 += rp[1];
        }
        if (ohalf){
          __half2 h = __floats2half2_rn(v0, v1);
          *(__half2*)(Ch + (size_t)r*N + c0) = h;
        } else {
          *(float2*)(Cf + (size_t)r*N + c0) = make_float2(v0, v1);
        }
      }
    }
  }
}

// ------------------------- channel attention (tensor-core) ------------------
__global__ __launch_bounds__(256) void attn_kernel(
    const __half* __restrict__ qh, const __half* __restrict__ kh,
    const __half* __restrict__ vt, const float* __restrict__ temp,
    const float* __restrict__ x, float* __restrict__ y)
{
  __shared__ float  Ps[64*65];
  __shared__ __half Ph[64*72];
  __shared__ __half Buf[128*72];
  const int bh = blockIdx.x;
  const int h = bh & 15;
  const size_t base = (size_t)bh * 32768;
  const int tid = threadIdx.x;
  const int lane = tid & 31, w = tid >> 5;
  __half* Qs = Buf;            // 64 x 72
  __half* Ks = Buf + 64*72;    // 64 x 72
  const uint32_t Qs32 = s2u32(Qs), Ks32 = s2u32(Ks);
  const uint32_t Ph32 = s2u32(Ph), Bf32 = s2u32(Buf);

  const int mrow = (w & 3) * 16;

  // ---- phase 1: S = Q K^T (f32 accum), warp tile 16x32 ----
  const int nb1 = (w >> 2) * 32;
  const uint32_t aoff = (uint32_t)(((mrow + (lane & 15))*72 + ((lane >> 4)*8))*2);
  uint32_t boff1[2];
  #pragma unroll
  for (int nt=0; nt<2; nt++)
    boff1[nt] = (uint32_t)(((nb1 + nt*16 + (lane & 7) + ((lane >> 4)*8))*72
                           + (((lane >> 3) & 1)*8))*2);

  float acc1[4][4];
  #pragma unroll
  for (int i=0;i<4;i++)
    #pragma unroll
    for (int j=0;j<4;j++) acc1[i][j]=0.f;

  const int lr = tid >> 2, lc = (tid & 3)*16;   // chunk loader: row 0..63, 16 cols
  for (int c = 0; c < 8; c++){
    const size_t gq = base + (size_t)lr*512 + c*64 + lc;
    *(uint4*)(Qs + lr*72 + lc)     = *(const uint4*)(qh + gq);
    *(uint4*)(Qs + lr*72 + lc + 8) = *(const uint4*)(qh + gq + 8);
    *(uint4*)(Ks + lr*72 + lc)     = *(const uint4*)(kh + gq);
    *(uint4*)(Ks + lr*72 + lc + 8) = *(const uint4*)(kh + gq + 8);
    __syncthreads();
    #pragma unroll
    for (int ks=0; ks<4; ks++){
      uint32_t a[4], bf[2][4];
      LDSM4(a[0], a[1], a[2], a[3], Qs32 + aoff + ks*32);
      #pragma unroll
      for (int nt=0; nt<2; nt++){
        LDSM4(bf[nt][0], bf[nt][1], bf[nt][2], bf[nt][3], Ks32 + boff1[nt] + ks*32);
        mma16(acc1[nt*2+0], a, &bf[nt][0]);
        mma16(acc1[nt*2+1], a, &bf[nt][2]);
      }
    }
    __syncthreads();
  }
  const float tmp = temp[h];
  #pragma unroll
  for (int nt=0; nt<4; nt++){
    const int col = nb1 + nt*8 + (lane & 3)*2;
    const int r0 = mrow + (lane >> 2);
    Ps[r0*65 + col]       = acc1[nt][0]*tmp;
    Ps[r0*65 + col + 1]   = acc1[nt][1]*tmp;
    Ps[(r0+8)*65 + col]   = acc1[nt][2]*tmp;
    Ps[(r0+8)*65 + col+1] = acc1[nt][3]*tmp;
  }
  __syncthreads();

  // ---- phase 2: softmax rows, P -> fp16 ----
  if (tid < 64){
    float* row = Ps + tid*65;
    float m = row[0];
    #pragma unroll 8
    for (int e=1;e<64;e++) m = fmaxf(m, row[e]);
    float s = 0.f;
    #pragma unroll 8
    for (int e=0;e<64;e++){ float ev = expf(row[e]-m); row[e]=ev; s+=ev; }
    float inv = 1.f/s;
    __half* pr = Ph + tid*72;
    #pragma unroll 8
    for (int e=0;e<64;e++) pr[e] = __float2half(row[e]*inv);
  }
  __syncthreads();

  // ---- phase 3: O = P @ Vt^T, warp tile 16x64, 4 chunks of 128 t-cols ----
  const int nb3 = (w >> 2) * 64;
  uint32_t boff3[4];
  #pragma unroll
  for (int nt=0; nt<4; nt++)
    boff3[nt] = (uint32_t)(((nb3 + nt*16 + (lane & 7) + ((lane >> 4)*8))*72
                           + (((lane >> 3) & 1)*8))*2);
  const int vr = tid >> 1, vc = (tid & 1)*32;   // Vt loader: 128 rows x 64 cols

  for (int nc = 0; nc < 4; nc++){
    const int t0 = nc*128;
    const size_t gv = base + (size_t)(t0 + vr)*64 + vc;
    *(uint4*)(Buf + vr*72 + vc)      = *(const uint4*)(vt + gv);
    *(uint4*)(Buf + vr*72 + vc + 8)  = *(const uint4*)(vt + gv + 8);
    *(uint4*)(Buf + vr*72 + vc + 16) = *(const uint4*)(vt + gv + 16);
    *(uint4*)(Buf + vr*72 + vc + 24) = *(const uint4*)(vt + gv + 24);
    __syncthreads();

    float acc2[8][4];
    #pragma unroll
    for (int i=0;i<8;i++)
      #pragma unroll
      for (int j=0;j<4;j++) acc2[i][j]=0.f;

    #pragma unroll
    for (int ks=0; ks<4; ks++){
      uint32_t a[4], bf[4][4];
      LDSM4(a[0], a[1], a[2], a[3], Ph32 + aoff + ks*32);
      #pragma unroll
      for (int nt=0; nt<4; nt++){
        LDSM4(bf[nt][0], bf[nt][1], bf[nt][2], bf[nt][3], Bf32 + boff3[nt] + ks*32);
        mma16(acc2[nt*2+0], a, &bf[nt][0]);
        mma16(acc2[nt*2+1], a, &bf[nt][2]);
      }
    }

    #pragma unroll
    for (int nt=0; nt<8; nt++){
      const int t = t0 + nb3 + nt*8 + (lane & 3)*2;
      const int d0 = mrow + (lane >> 2);
      #pragma unroll
      for (int rr=0; rr<2; rr++){
        const int d = d0 + rr*8;
        const size_t o = base + (size_t)d*512 + t;
        y[o]   = acc2[nt][rr*2+0] + x[o];
        y[o+1] = acc2[nt][rr*2+1] + x[o+1];
      }
    }
    __syncthreads();
  }
}

// ------------------------- launch ------------------------------------------
static void launch_gemm(const __half* A, const __half* Bt, const float* bias,
                        const float* R, void* C, int M, int N, int K,
                        int act, int conv, int ohalf){
  dim3 grid(N/BN, M/BM);
  gemm_kernel<<<grid, 256, GEMM_SMEM_BYTES>>>(A, Bt, bias, R, C, M, N, K, act, conv, ohalf);
}
static void launch_tcopy(const float* src, __half* dst, int R, int C){
  dim3 grid(C/32, R/32), block(32,8);
  tcopy_kernel<<<grid, block>>>(src, dst, R, C);
}

extern "C" void kernel_launch(void* const* d_in, const int* in_sizes, int n_in,
                              void* d_out, int out_size) {
  const float* x       = (const float*)d_in[0];
  const float* q_w     = (const float*)d_in[1];
  const float* q_b     = (const float*)d_in[2];
  const float* k_w     = (const float*)d_in[3];
  const float* k_b     = (const float*)d_in[4];
  const float* v_w     = (const float*)d_in[5];
  const float* v_b     = (const float*)d_in[6];
  const float* temp    = (const float*)d_in[7];
  const float* ln1_w   = (const float*)d_in[8];
  const float* ln1_b   = (const float*)d_in[9];
  const float* ln2_w   = (const float*)d_in[10];
  const float* ln2_b   = (const float*)d_in[11];
  const float* ln3_w   = (const float*)d_in[12];
  const float* ln3_b   = (const float*)d_in[13];
  const float* ln4_w   = (const float*)d_in[14];
  const float* ln4_b   = (const float*)d_in[15];
  const float* lin1_w  = (const float*)d_in[16];
  const float* lin1_b  = (const float*)d_in[17];
  const float* lin2_w  = (const float*)d_in[18];
  const float* lin2_b  = (const float*)d_in[19];
  const float* mlp1_w1 = (const float*)d_in[20];
  const float* mlp1_b1 = (const float*)d_in[21];
  const float* mlp1_w2 = (const float*)d_in[22];
  const float* mlp1_b2 = (const float*)d_in[23];
  const float* mlp2_w1 = (const float*)d_in[24];
  const float* mlp2_b1 = (const float*)d_in[25];
  const float* mlp2_w2 = (const float*)d_in[26];
  const float* mlp2_b2 = (const float*)d_in[27];
  const float* conv1_w = (const float*)d_in[28];
  const float* conv1_b = (const float*)d_in[29];
  const float* conv2_w = (const float*)d_in[30];
  const float* conv2_b = (const float*)d_in[31];
  float* out = (float*)d_out;

  cudaFuncSetAttribute(gemm_kernel, cudaFuncAttributeMaxDynamicSharedMemorySize, GEMM_SMEM_BYTES);

  __half *p_ln, *p_wide, *p_dy, *p_c1, *p_qh, *p_kh, *p_vh, *p_vt;
  float  *p_y, *p_y2, *p_b2f;
  __half *p_MT, *p_MinvA, *p_W1fT, *p_W2fT, *p_Bc1t, *p_Bc2t;
  __half *p_qwt, *p_kwt, *p_vwt, *p_lin1t, *p_lin2r, *p_m11t, *p_m12t, *p_m21t, *p_m22t;
  cudaGetSymbolAddress((void**)&p_ln,   g_ln);
  cudaGetSymbolAddress((void**)&p_wide, g_wide);
  cudaGetSymbolAddress((void**)&p_dy,   g_dy);
  cudaGetSymbolAddress((void**)&p_c1,   g_c1);
  cudaGetSymbolAddress((void**)&p_qh,   g_qh);
  cudaGetSymbolAddress((void**)&p_kh,   g_kh);
  cudaGetSymbolAddress((void**)&p_vh,   g_vh);
  cudaGetSymbolAddress((void**)&p_vt,   g_vt);
  cudaGetSymbolAddress((void**)&p_y,    g_y);
  cudaGetSymbolAddress((void**)&p_y2,   g_y2);
  cudaGetSymbolAddress((void**)&p_b2f,  g_b2f);
  cudaGetSymbolAddress((void**)&p_MT,   g_MT);
  cudaGetSymbolAddress((void**)&p_MinvA,g_MinvA);
  cudaGetSymbolAddress((void**)&p_W1fT, g_W1fT);
  cudaGetSymbolAddress((void**)&p_W2fT, g_W2fT);
  cudaGetSymbolAddress((void**)&p_Bc1t, g_Bc1t);
  cudaGetSymbolAddress((void**)&p_Bc2t, g_Bc2t);
  cudaGetSymbolAddress((void**)&p_qwt,  g_qwt);
  cudaGetSymbolAddress((void**)&p_kwt,  g_kwt);
  cudaGetSymbolAddress((void**)&p_vwt,  g_vwt);
  cudaGetSymbolAddress((void**)&p_lin1t,g_lin1t);
  cudaGetSymbolAddress((void**)&p_lin2r,g_lin2r);
  cudaGetSymbolAddress((void**)&p_m11t, g_m11t);
  cudaGetSymbolAddress((void**)&p_m12t, g_m12t);
  cudaGetSymbolAddress((void**)&p_m21t, g_m21t);
  cudaGetSymbolAddress((void**)&p_m22t, g_m22t);

  // attention block; launch index 3 = Q-projection GEMM (profiling target)
  ln_kernel<<<TOK, 256>>>(x, ln1_w, ln1_b, p_ln);                               // 0
  launch_tcopy(q_w, p_qwt, DMODEL, DMODEL);                                     // 1
  launch_tcopy(k_w, p_kwt, DMODEL, DMODEL);                                     // 2
  launch_gemm(p_ln, p_qwt, q_b, nullptr, p_qh, TOK, DMODEL, DMODEL, 0, 0, 1);   // 3
  launch_tcopy(v_w, p_vwt, DMODEL, DMODEL);                                     // 4
  launch_gemm(p_ln, p_kwt, k_b, nullptr, p_kh, TOK, DMODEL, DMODEL, 0, 0, 1);
  launch_gemm(p_ln, p_vwt, v_b, nullptr, p_vh, TOK, DMODEL, DMODEL, 0, 0, 1);
  vtrans_kernel<<<dim3(16,2,512), dim3(32,8)>>>(p_vh, p_vt);
  attn_kernel<<<512, 256>>>(p_qh, p_kh, p_vt, temp, x, p_y);

  // prep: DCT folds + weight transposes + conv packs
  build_dct_kernel<<<4096, 256>>>();
  launch_tcopy(lin1_w, p_lin1t, DMODEL, DFF);
  rcopy_kernel<<<(DFF*DMODEL)/1024, 256>>>(lin2_w, p_lin2r);
  launch_tcopy(mlp1_w1, p_m11t, DMODEL, DFF);
  launch_tcopy(mlp1_w2, p_m12t, DFF, DMODEL);
  launch_tcopy(mlp2_w1, p_m21t, DMODEL, DFF);
  launch_tcopy(mlp2_w2, p_m22t, DFF, DMODEL);
  pack_conv_kernel<<<12288, 256>>>(conv1_w, p_Bc1t);
  pack_conv_kernel<<<12288, 256>>>(conv2_w, p_Bc2t);
  launch_gemm(p_lin1t, p_MT,    nullptr, nullptr, p_W1fT, DFF,    DMODEL, DMODEL, 0, 0, 1);
  launch_gemm(p_MinvA, p_lin2r, nullptr, nullptr, p_W2fT, DMODEL, DFF,    DMODEL, 0, 0, 1);
  fold_bias_kernel<<<DMODEL, 256>>>(lin2_b);

  // DCT-folded MLP
  ln_kernel<<<TOK, 256>>>(p_y, ln2_w, ln2_b, p_ln);
  launch_gemm(p_ln,   p_W1fT, lin1_b, nullptr, p_wide, TOK, DFF,    DMODEL, 1, 0, 1);
  launch_gemm(p_wide, p_W2fT, p_b2f,  nullptr, p_dy,   TOK, DMODEL, DFF,    0, 0, 1);

  // mlp1(d_y) + y
  launch_gemm(p_dy,   p_m11t, mlp1_b1, nullptr, p_wide, TOK, DFF,    DMODEL, 1, 0, 1);
  launch_gemm(p_wide, p_m12t, mlp1_b2, p_y,     p_y2,   TOK, DMODEL, DFF,    0, 0, 0);

  // mlp2(ln3(y)) added
  ln_kernel<<<TOK, 256>>>(p_y, ln3_w, ln3_b, p_ln);
  launch_gemm(p_ln,   p_m21t, mlp2_b1, nullptr, p_wide, TOK, DFF,    DMODEL, 1, 0, 1);
  launch_gemm(p_wide, p_m22t, mlp2_b2, p_y2,    p_y2,   TOK, DMODEL, DFF,    0, 0, 0);

  // conv path (shifted GEMMs, K=3072), silu between; final residual y2
  ln_kernel<<<TOK, 256>>>(p_y2, ln4_w, ln4_b, p_ln);
  launch_gemm(p_ln, p_Bc1t, conv1_b, nullptr, p_c1, TOK, DMODEL, 3*DMODEL, 2, 1, 1);
  launch_gemm(p_c1, p_Bc2t, conv2_b, p_y2,    out,  TOK, DMODEL, 3*DMODEL, 0, 1, 0);
}